// round 2
// baseline (speedup 1.0000x reference)
#include <cuda_runtime.h>
#include <cuda_bf16.h>
#include <cstdint>

// ---------------------------------------------------------------------------
// Fused RV-linear layer (no tcgen05 — harness PTX targets sm_103 non-'a',
// so tensor work goes through mma.sync HMMA which is arch-unconditional):
//   mu    = x @ w_mu + b_mu                                       (B,128)
//   sigma = (sum_i x_i^2 * softplus(w_sigma)_i) + softplus(b_sigma) (B,128)
//   kl    = -0.5 * ( sum_o(log spw_o - spw_o) - sum|w_mu| )
// fp32 accuracy via hi/lo bf16 split: x=xh+xl, w=wh+wl,
// mu ≈ xh*wh + xl*wh + xh*wl   (lo*lo term ~2^-18 relative, negligible)
// ---------------------------------------------------------------------------

#define NTHREADS 256
#define TILE_M   128

// ---- dynamic shared memory layout (bytes) ----
#define SM_QROW  0                 // 128 floats
#define SM_SPW   512               // 128 floats
#define SM_SPB   1024
#define SM_BMU   1536
#define SM_RED   2048              // 16 floats
#define SM_BH    2112              // 128*68 uint32 = 34816 B (bf16x2 pairs, hi)
#define SM_BL    (2112 + 34816)    // same, lo
#define SMEM_TOTAL (SM_BL + 34816) // 71744 B
#define BSTRIDE  68                // words per n-row; (4n+p)%32 conflict-free frag LDS

__device__ __forceinline__ uint32_t pack_bf16x2(float lo, float hi) {
    // result: low 16 bits = bf16(lo), high 16 bits = bf16(hi)
    uint32_t r;
    asm("cvt.rn.bf16x2.f32 %0, %1, %2;" : "=r"(r) : "f"(hi), "f"(lo));
    return r;
}
__device__ __forceinline__ float bf_lo(uint32_t u) { return __uint_as_float(u << 16); }
__device__ __forceinline__ float bf_hi(uint32_t u) { return __uint_as_float(u & 0xffff0000u); }

__device__ __forceinline__ void mma16816(float* d, uint32_t a0, uint32_t a1,
                                         uint32_t a2, uint32_t a3,
                                         uint32_t b0, uint32_t b1) {
    asm volatile(
        "mma.sync.aligned.m16n8k16.row.col.f32.bf16.bf16.f32 "
        "{%0,%1,%2,%3}, {%4,%5,%6,%7}, {%8,%9}, {%0,%1,%2,%3};"
        : "+f"(d[0]), "+f"(d[1]), "+f"(d[2]), "+f"(d[3])
        : "r"(a0), "r"(a1), "r"(a2), "r"(a3), "r"(b0), "r"(b1));
}

// ---------------------------------------------------------------------------
__global__ void __launch_bounds__(NTHREADS, 2)
rvlinear_kernel(const float* __restrict__ x,
                const float* __restrict__ w_mu,
                const float* __restrict__ w_sigma,
                const float* __restrict__ b_mu,
                const float* __restrict__ b_sigma,
                float* __restrict__ out_mu,
                float* __restrict__ out_sigma,
                float* __restrict__ out_kl) {
    extern __shared__ __align__(16) char smem[];
    float*    qrow = (float*)(smem + SM_QROW);
    float*    spw  = (float*)(smem + SM_SPW);
    float*    spb  = (float*)(smem + SM_SPB);
    float*    bmu  = (float*)(smem + SM_BMU);
    float*    red  = (float*)(smem + SM_RED);
    uint32_t* Bh   = (uint32_t*)(smem + SM_BH);
    uint32_t* Bl   = (uint32_t*)(smem + SM_BL);

    const int tid  = threadIdx.x;
    const int warp = tid >> 5;
    const int lane = tid & 31;

    if (tid < 128) {
        spw[tid] = log1pf(expf(w_sigma[tid]));
        spb[tid] = log1pf(expf(b_sigma[tid]));
        bmu[tid] = b_mu[tid];
    }

    // ---- build B = w_mu^T as bf16x2 (k-pair) hi/lo in SMEM ----
    // unit (p, n4): kpair p (k=2p,2p+1), col block n0=4*n4
    // lane mapping keeps LDG coalesced (8 lanes x 16B contiguous per k-row)
    {
        const int nsub = lane & 7;        // 0..7
        const int psub = lane >> 3;       // 0..3
        const int n4b  = nsub + 8 * (warp & 3);    // 0..31
        const int pb   = psub + 4 * (warp >> 2);   // 0..7
#pragma unroll
        for (int j = 0; j < 8; j++) {
            const int p  = pb + 8 * j;    // 0..63
            const int n0 = 4 * n4b;
            float4 w0 = *(const float4*)(w_mu + (2 * p) * 128 + n0);
            float4 w1 = *(const float4*)(w_mu + (2 * p + 1) * 128 + n0);
            float a[4] = {w0.x, w0.y, w0.z, w0.w};
            float b[4] = {w1.x, w1.y, w1.z, w1.w};
#pragma unroll
            for (int dn = 0; dn < 4; dn++) {
                uint32_t h = pack_bf16x2(a[dn], b[dn]);
                uint32_t l = pack_bf16x2(a[dn] - bf_lo(h), b[dn] - bf_hi(h));
                const int n = n0 + dn;
                Bh[n * BSTRIDE + p] = h;
                Bl[n * BSTRIDE + p] = l;
            }
        }
    }
    __syncthreads();

    // ---- main GEMM: warp owns rows [warp*16, warp*16+16), all 128 cols ----
    const int r0g = blockIdx.x * TILE_M + warp * 16 + (lane >> 2);
    const float* xr0 = x + (size_t)r0g * 128;
    const float* xr1 = xr0 + 8 * 128;

    float acc[16][4];
#pragma unroll
    for (int t = 0; t < 16; t++) {
        acc[t][0] = 0.f; acc[t][1] = 0.f; acc[t][2] = 0.f; acc[t][3] = 0.f;
    }

    float q0 = 0.f, q1 = 0.f;   // quadratic form partials, rows r0 and r0+8

    for (int s = 0; s < 8; s++) {
        const int c0 = 16 * s + 2 * (lane & 3);
        // A fragment loads (global, 32B-sector coalesced per 4-lane group)
        float2 x00 = *(const float2*)(xr0 + c0);
        float2 x01 = *(const float2*)(xr0 + c0 + 8);
        float2 x10 = *(const float2*)(xr1 + c0);
        float2 x11 = *(const float2*)(xr1 + c0 + 8);

        // quadratic form on fp32 x (exact)
        float2 sa = *(const float2*)(spw + c0);
        float2 sb2 = *(const float2*)(spw + c0 + 8);
        q0 += x00.x * x00.x * sa.x + x00.y * x00.y * sa.y
            + x01.x * x01.x * sb2.x + x01.y * x01.y * sb2.y;
        q1 += x10.x * x10.x * sa.x + x10.y * x10.y * sa.y
            + x11.x * x11.x * sb2.x + x11.y * x11.y * sb2.y;

        // hi/lo split
        uint32_t ah0 = pack_bf16x2(x00.x, x00.y);
        uint32_t ah1 = pack_bf16x2(x10.x, x10.y);
        uint32_t ah2 = pack_bf16x2(x01.x, x01.y);
        uint32_t ah3 = pack_bf16x2(x11.x, x11.y);
        uint32_t al0 = pack_bf16x2(x00.x - bf_lo(ah0), x00.y - bf_hi(ah0));
        uint32_t al1 = pack_bf16x2(x10.x - bf_lo(ah1), x10.y - bf_hi(ah1));
        uint32_t al2 = pack_bf16x2(x01.x - bf_lo(ah2), x01.y - bf_hi(ah2));
        uint32_t al3 = pack_bf16x2(x11.x - bf_lo(ah3), x11.y - bf_hi(ah3));

        const int prow = 8 * s + (lane & 3);
#pragma unroll
        for (int t = 0; t < 16; t++) {
            const int nb = (t * 8 + (lane >> 2)) * BSTRIDE;
            uint32_t bh0 = Bh[nb + prow];
            uint32_t bh1 = Bh[nb + prow + 4];
            mma16816(acc[t], ah0, ah1, ah2, ah3, bh0, bh1);  // xh*wh
            mma16816(acc[t], al0, al1, al2, al3, bh0, bh1);  // xl*wh
            uint32_t bl0 = Bl[nb + prow];
            uint32_t bl1 = Bl[nb + prow + 4];
            mma16816(acc[t], ah0, ah1, ah2, ah3, bl0, bl1);  // xh*wl
        }
    }

    // ---- quad reduce across the 4 lanes sharing a row ----
    q0 += __shfl_xor_sync(0xffffffffu, q0, 1);
    q0 += __shfl_xor_sync(0xffffffffu, q0, 2);
    q1 += __shfl_xor_sync(0xffffffffu, q1, 1);
    q1 += __shfl_xor_sync(0xffffffffu, q1, 2);
    if ((lane & 3) == 0) {
        qrow[warp * 16 + (lane >> 2)]     = q0;
        qrow[warp * 16 + (lane >> 2) + 8] = q1;
    }

    // ---- mu epilogue: direct STG.64 (full 32B sectors per 4-lane group) ----
    {
        float* om0 = out_mu + (size_t)r0g * 128;
        float* om1 = om0 + 8 * 128;
#pragma unroll
        for (int t = 0; t < 16; t++) {
            const int c = t * 8 + 2 * (lane & 3);
            float2 bm = *(const float2*)(bmu + c);
            float2 v0 = make_float2(acc[t][0] + bm.x, acc[t][1] + bm.y);
            float2 v1 = make_float2(acc[t][2] + bm.x, acc[t][3] + bm.y);
            *(float2*)(om0 + c) = v0;
            *(float2*)(om1 + c) = v1;
        }
    }

    __syncthreads();

    // ---- sigma output (coalesced float4) ----
    {
        float* osig = out_sigma + (size_t)blockIdx.x * (TILE_M * 128);
#pragma unroll
        for (int j = 0; j < 16; j++) {
            const int idx = j * NTHREADS + tid;
            const int row = idx >> 5;
            const int c   = (idx & 31) << 2;
            const float q = qrow[row];
            float4 sp = *(const float4*)(spb + c);
            float4 o = make_float4(q + sp.x, q + sp.y, q + sp.z, q + sp.w);
            *(float4*)(osig + row * 128 + c) = o;
        }
    }

    // ---- KL scalar (block 0 only) ----
    if (blockIdx.x == 0) {
        float s = 0.f;
        for (int i = tid; i < 16384; i += NTHREADS) s += fabsf(w_mu[i]);
#pragma unroll
        for (int o = 16; o; o >>= 1) s += __shfl_xor_sync(0xffffffffu, s, o);

        float r = 0.f;
        if (tid < 128) {
            float sw = spw[tid];
            r = logf(sw) - sw;
        }
#pragma unroll
        for (int o = 16; o; o >>= 1) r += __shfl_xor_sync(0xffffffffu, r, o);

        if (lane == 0) { red[warp] = s; red[8 + warp] = r; }
        __syncthreads();
        if (tid == 0) {
            float S = 0.f, R = 0.f;
            for (int w2 = 0; w2 < 8; w2++) { S += red[w2]; R += red[8 + w2]; }
            out_kl[0] = -0.5f * (R - S);
        }
    }
}

// ---------------------------------------------------------------------------
extern "C" void kernel_launch(void* const* d_in, const int* in_sizes, int n_in,
                              void* d_out, int out_size) {
    const float* x       = (const float*)d_in[0];
    const float* w_mu    = (const float*)d_in[1];
    const float* w_sigma = (const float*)d_in[2];
    const float* b_mu    = (const float*)d_in[3];
    const float* b_sigma = (const float*)d_in[4];

    const int batch = in_sizes[0] / 128;
    float* out       = (float*)d_out;
    float* out_mu    = out;
    float* out_sigma = out + (size_t)batch * 128;
    float* out_kl    = out + (size_t)batch * 256;

    cudaFuncSetAttribute(rvlinear_kernel,
                         cudaFuncAttributeMaxDynamicSharedMemorySize, SMEM_TOTAL);
    rvlinear_kernel<<<batch / TILE_M, NTHREADS, SMEM_TOTAL>>>(
        x, w_mu, w_sigma, b_mu, b_sigma, out_mu, out_sigma, out_kl);
}

// round 4
// speedup vs baseline: 1.0132x; 1.0132x over previous
#include <cuda_runtime.h>
#include <cuda_bf16.h>
#include <cstdint>

// ---------------------------------------------------------------------------
// Fused RV-linear layer (HMMA mma.sync path; tcgen05 not available on the
// harness's non-'a' PTX target):
//   mu    = x @ w_mu + b_mu
//   sigma = (sum_i x_i^2 * softplus(w_sigma)_i) + softplus(b_sigma)
//   kl    = -0.5 * ( sum_o(log spw_o - spw_o) - sum|w_mu| )
// fp32 accuracy via hi/lo bf16 split, 3 accumulated passes.
// R3/R4: warp tile 32x64 (4x2 warp grid) to halve B SMEM traffic (L1 was 75.7%).
// ---------------------------------------------------------------------------

#define NTHREADS 256
#define TILE_M   128

// ---- dynamic shared memory layout (bytes) ----
#define SM_QROW  0                 // 128 floats
#define SM_SPW   512               // 128 floats
#define SM_SPB   1024
#define SM_BMU   1536
#define SM_RED   2048              // 16 floats
#define SM_BH    2112              // 128*68 uint32 = 34816 B (bf16x2 k-pairs, hi)
#define SM_BL    (2112 + 34816)    // same, lo
#define SMEM_TOTAL (SM_BL + 34816) // 71744 B
#define BSTRIDE  68                // 68 % 32 == 4 -> (4*n + p) banks, conflict-free

__device__ __forceinline__ uint32_t pack_bf16x2(float lo, float hi) {
    uint32_t r;
    asm("cvt.rn.bf16x2.f32 %0, %1, %2;" : "=r"(r) : "f"(hi), "f"(lo));
    return r;
}
__device__ __forceinline__ float bf_lo(uint32_t u) { return __uint_as_float(u << 16); }
__device__ __forceinline__ float bf_hi(uint32_t u) { return __uint_as_float(u & 0xffff0000u); }

__device__ __forceinline__ void mma16816(float* d, uint32_t a0, uint32_t a1,
                                         uint32_t a2, uint32_t a3,
                                         uint32_t b0, uint32_t b1) {
    asm volatile(
        "mma.sync.aligned.m16n8k16.row.col.f32.bf16.bf16.f32 "
        "{%0,%1,%2,%3}, {%4,%5,%6,%7}, {%8,%9}, {%0,%1,%2,%3};"
        : "+f"(d[0]), "+f"(d[1]), "+f"(d[2]), "+f"(d[3])
        : "r"(a0), "r"(a1), "r"(a2), "r"(a3), "r"(b0), "r"(b1));
}

// ---------------------------------------------------------------------------
__global__ void __launch_bounds__(NTHREADS, 2)
rvlinear_kernel(const float* __restrict__ x,
                const float* __restrict__ w_mu,
                const float* __restrict__ w_sigma,
                const float* __restrict__ b_mu,
                const float* __restrict__ b_sigma,
                float* __restrict__ out_mu,
                float* __restrict__ out_sigma,
                float* __restrict__ out_kl) {
    extern __shared__ __align__(16) char smem[];
    float*    qrow = (float*)(smem + SM_QROW);
    float*    spw  = (float*)(smem + SM_SPW);
    float*    spb  = (float*)(smem + SM_SPB);
    float*    bmu  = (float*)(smem + SM_BMU);
    float*    red  = (float*)(smem + SM_RED);
    uint32_t* Bh   = (uint32_t*)(smem + SM_BH);
    uint32_t* Bl   = (uint32_t*)(smem + SM_BL);

    const int tid  = threadIdx.x;
    const int warp = tid >> 5;
    const int lane = tid & 31;

    if (tid < 128) {
        spw[tid] = log1pf(expf(w_sigma[tid]));
        spb[tid] = log1pf(expf(b_sigma[tid]));
        bmu[tid] = b_mu[tid];
    }

    // ---- build B = w_mu^T as bf16x2 (k-pair) hi/lo in SMEM ----
    {
        const int nsub = lane & 7;                 // 0..7
        const int psub = lane >> 3;                // 0..3
        const int n4b  = nsub + 8 * (warp & 3);    // 0..31
        const int pb   = psub + 4 * (warp >> 2);   // 0..7
#pragma unroll
        for (int j = 0; j < 8; j++) {
            const int p  = pb + 8 * j;             // kpair 0..63
            const int n0 = 4 * n4b;
            float4 w0 = *(const float4*)(w_mu + (2 * p) * 128 + n0);
            float4 w1 = *(const float4*)(w_mu + (2 * p + 1) * 128 + n0);
            float a[4] = {w0.x, w0.y, w0.z, w0.w};
            float b[4] = {w1.x, w1.y, w1.z, w1.w};
#pragma unroll
            for (int dn = 0; dn < 4; dn++) {
                uint32_t h = pack_bf16x2(a[dn], b[dn]);
                uint32_t l = pack_bf16x2(a[dn] - bf_lo(h), b[dn] - bf_hi(h));
                const int n = n0 + dn;
                Bh[n * BSTRIDE + p] = h;
                Bl[n * BSTRIDE + p] = l;
            }
        }
    }
    __syncthreads();

    // ---- main GEMM: 4x2 warp grid; warp tile = 32 rows x 64 cols ----
    const int wm = warp & 3;       // M group (32 rows)
    const int wn = warp >> 2;      // N half (64 cols)
    const int rb = blockIdx.x * TILE_M + wm * 32 + (lane >> 2);
    const float* xr = x + (size_t)rb * 128;

    float acc[2][8][4];
#pragma unroll
    for (int mt = 0; mt < 2; mt++)
#pragma unroll
        for (int t = 0; t < 8; t++) {
            acc[mt][t][0] = 0.f; acc[mt][t][1] = 0.f;
            acc[mt][t][2] = 0.f; acc[mt][t][3] = 0.f;
        }

    float q[4] = {0.f, 0.f, 0.f, 0.f};   // quad partials for rows rb+{0,8,16,24}

    for (int s = 0; s < 8; s++) {
        const int c0 = 16 * s + 2 * (lane & 3);
        float2 xv[4][2];
#pragma unroll
        for (int o = 0; o < 4; o++) {
            xv[o][0] = *(const float2*)(xr + (size_t)(8 * o) * 128 + c0);
            xv[o][1] = *(const float2*)(xr + (size_t)(8 * o) * 128 + c0 + 8);
        }

        if (wn == 0) {
            float2 sa = *(const float2*)(spw + c0);
            float2 sb2 = *(const float2*)(spw + c0 + 8);
#pragma unroll
            for (int o = 0; o < 4; o++) {
                q[o] += xv[o][0].x * xv[o][0].x * sa.x
                      + xv[o][0].y * xv[o][0].y * sa.y
                      + xv[o][1].x * xv[o][1].x * sb2.x
                      + xv[o][1].y * xv[o][1].y * sb2.y;
            }
        }

        // hi/lo split: a-frag words per m-tile [a0,a1,a2,a3]
        uint32_t ah[2][4], al[2][4];
#pragma unroll
        for (int mt = 0; mt < 2; mt++) {
            const int o0 = 2 * mt, o1 = 2 * mt + 1;
            ah[mt][0] = pack_bf16x2(xv[o0][0].x, xv[o0][0].y);
            ah[mt][1] = pack_bf16x2(xv[o1][0].x, xv[o1][0].y);
            ah[mt][2] = pack_bf16x2(xv[o0][1].x, xv[o0][1].y);
            ah[mt][3] = pack_bf16x2(xv[o1][1].x, xv[o1][1].y);
            al[mt][0] = pack_bf16x2(xv[o0][0].x - bf_lo(ah[mt][0]),
                                    xv[o0][0].y - bf_hi(ah[mt][0]));
            al[mt][1] = pack_bf16x2(xv[o1][0].x - bf_lo(ah[mt][1]),
                                    xv[o1][0].y - bf_hi(ah[mt][1]));
            al[mt][2] = pack_bf16x2(xv[o0][1].x - bf_lo(ah[mt][2]),
                                    xv[o0][1].y - bf_hi(ah[mt][2]));
            al[mt][3] = pack_bf16x2(xv[o1][1].x - bf_lo(ah[mt][3]),
                                    xv[o1][1].y - bf_hi(ah[mt][3]));
        }

        const int prow = 8 * s + (lane & 3);
#pragma unroll
        for (int t = 0; t < 8; t++) {
            const int nb = (wn * 64 + t * 8 + (lane >> 2)) * BSTRIDE;
            uint32_t bh0 = Bh[nb + prow];
            uint32_t bh1 = Bh[nb + prow + 4];
            uint32_t bl0 = Bl[nb + prow];
            uint32_t bl1 = Bl[nb + prow + 4];
#pragma unroll
            for (int mt = 0; mt < 2; mt++) {
                mma16816(acc[mt][t], ah[mt][0], ah[mt][1], ah[mt][2], ah[mt][3], bh0, bh1);
                mma16816(acc[mt][t], al[mt][0], al[mt][1], al[mt][2], al[mt][3], bh0, bh1);
                mma16816(acc[mt][t], ah[mt][0], ah[mt][1], ah[mt][2], ah[mt][3], bl0, bl1);
            }
        }
    }

    // ---- quad reduce across the 4 lanes sharing each row ----
    if (wn == 0) {
#pragma unroll
        for (int o = 0; o < 4; o++) {
            q[o] += __shfl_xor_sync(0xffffffffu, q[o], 1);
            q[o] += __shfl_xor_sync(0xffffffffu, q[o], 2);
        }
        if ((lane & 3) == 0) {
            const int r = wm * 32 + (lane >> 2);
#pragma unroll
            for (int o = 0; o < 4; o++) qrow[r + 8 * o] = q[o];
        }
    }

    // ---- mu epilogue: direct float2 stores ----
    {
        float* om = out_mu + (size_t)rb * 128;
#pragma unroll
        for (int mt = 0; mt < 2; mt++) {
#pragma unroll
            for (int t = 0; t < 8; t++) {
                const int c = wn * 64 + t * 8 + 2 * (lane & 3);
                float2 bm = *(const float2*)(bmu + c);
                *(float2*)(om + (size_t)(mt * 16) * 128 + c) =
                    make_float2(acc[mt][t][0] + bm.x, acc[mt][t][1] + bm.y);
                *(float2*)(om + (size_t)(mt * 16 + 8) * 128 + c) =
                    make_float2(acc[mt][t][2] + bm.x, acc[mt][t][3] + bm.y);
            }
        }
    }

    __syncthreads();

    // ---- sigma output (coalesced float4) ----
    {
        float* osig = out_sigma + (size_t)blockIdx.x * (TILE_M * 128);
#pragma unroll
        for (int j = 0; j < 16; j++) {
            const int idx = j * NTHREADS + tid;
            const int row = idx >> 5;
            const int c   = (idx & 31) << 2;
            const float qv = qrow[row];
            float4 sp = *(const float4*)(spb + c);
            *(float4*)(osig + row * 128 + c) =
                make_float4(qv + sp.x, qv + sp.y, qv + sp.z, qv + sp.w);
        }
    }

    // ---- KL scalar (block 0 only) ----
    if (blockIdx.x == 0) {
        float s = 0.f;
        for (int i = tid; i < 16384; i += NTHREADS) s += fabsf(w_mu[i]);
#pragma unroll
        for (int o = 16; o; o >>= 1) s += __shfl_xor_sync(0xffffffffu, s, o);

        float r = 0.f;
        if (tid < 128) {
            float sw = spw[tid];
            r = logf(sw) - sw;
        }
#pragma unroll
        for (int o = 16; o; o >>= 1) r += __shfl_xor_sync(0xffffffffu, r, o);

        if (lane == 0) { red[warp] = s; red[8 + warp] = r; }
        __syncthreads();
        if (tid == 0) {
            float S = 0.f, R = 0.f;
            for (int w2 = 0; w2 < 8; w2++) { S += red[w2]; R += red[8 + w2]; }
            out_kl[0] = -0.5f * (R - S);
        }
    }
}

// ---------------------------------------------------------------------------
extern "C" void kernel_launch(void* const* d_in, const int* in_sizes, int n_in,
                              void* d_out, int out_size) {
    const float* x       = (const float*)d_in[0];
    const float* w_mu    = (const float*)d_in[1];
    const float* w_sigma = (const float*)d_in[2];
    const float* b_mu    = (const float*)d_in[3];
    const float* b_sigma = (const float*)d_in[4];

    const int batch = in_sizes[0] / 128;
    float* out       = (float*)d_out;
    float* out_mu    = out;
    float* out_sigma = out + (size_t)batch * 128;
    float* out_kl    = out + (size_t)batch * 256;

    cudaFuncSetAttribute(rvlinear_kernel,
                         cudaFuncAttributeMaxDynamicSharedMemorySize, SMEM_TOTAL);
    rvlinear_kernel<<<batch / TILE_M, NTHREADS, SMEM_TOTAL>>>(
        x, w_mu, w_sigma, b_mu, b_sigma, out_mu, out_sigma, out_kl);
}